// round 16
// baseline (speedup 1.0000x reference)
#include <cuda_runtime.h>
#include <cuda_fp16.h>
#include <cuda_bf16.h>

// out[row[e]] += values[e] * x[col[e]],  row sorted ascending.
// E = 1.6M, N = 100k, D = 64.
//
// Edge-balanced, persistent, SOFTWARE-BATCHED:
//   - warp-task = 4 groups x 8 lanes; group owns CHUNK=16 consecutive edges.
//   - lane fl gathers one uint4 (16B fp16) per edge; 8 lanes = full 128B row.
//   - batches of 4 steps: phase 1 issues 4 col/val/row loads then 4 gathers
//     back-to-back (MLP=4/warp; ballot no longer fences every load),
//     phase 2 does FMAs + ballot-gated red.global.add.v4.f32 flushes.
//   - persistent 1216-block grid: no wave quantization.
// Prep (1 fused kernel): x->fp16 convert + out zero-init.

#define N_NODES 100000
#define D_FEAT 64
#define CHUNK 16
#define BATCH 4

__device__ __align__(256) __half g_x_half[(size_t)N_NODES * D_FEAT];

__global__ void __launch_bounds__(256) fused_prep_kernel(
    const float* __restrict__ x, int n4,   // convert job: n4 = floats/4
    float* __restrict__ out, int n_out4,   // zero job: out_size/4
    int conv_blocks)
{
    if ((int)blockIdx.x < conv_blocks) {
        int i = blockIdx.x * blockDim.x + threadIdx.x;
        if (i >= n4) return;
        float4 f = __ldg(&((const float4*)x)[i]);
        __half2 h0 = __floats2half2_rn(f.x, f.y);
        __half2 h1 = __floats2half2_rn(f.z, f.w);
        uint2 packed;
        packed.x = *(unsigned*)&h0;
        packed.y = *(unsigned*)&h1;
        ((uint2*)g_x_half)[i] = packed;
    } else {
        int i = (blockIdx.x - conv_blocks) * blockDim.x + threadIdx.x;
        if (i >= n_out4) return;
        ((float4*)out)[i] = make_float4(0.f, 0.f, 0.f, 0.f);
    }
}

__device__ __forceinline__ void red_add_v4(float* addr, float a, float b,
                                           float c, float d, int pred) {
    asm volatile(
        "{\n\t"
        ".reg .pred p;\n\t"
        "setp.ne.s32 p, %0, 0;\n\t"
        "@p red.global.add.v4.f32 [%1], {%2, %3, %4, %5};\n\t"
        "}" :: "r"(pred), "l"(addr), "f"(a), "f"(b), "f"(c), "f"(d) : "memory");
}

__global__ void __launch_bounds__(256) spmm_edge_chunk_kernel(
    const int* __restrict__ row,
    const int* __restrict__ col,
    const float* __restrict__ val,
    float* __restrict__ out,
    int n_edges, int n_tasks)
{
    int lane = threadIdx.x & 31;
    int wid  = threadIdx.x >> 5;
    int grp  = lane >> 3;           // which 16-edge chunk of this warp-task
    int fl   = lane & 7;            // owns fp16 feats [8*fl, 8*fl+8)

    const uint4* __restrict__ xq = (const uint4*)g_x_half;  // 8 uint4 per row
    int warps_per_grid = gridDim.x * (blockDim.x >> 5);

    for (int task = blockIdx.x * (blockDim.x >> 5) + wid;
         task < n_tasks;
         task += warps_per_grid) {

        int warp_base = task * (4 * CHUNK);
        int base = warp_base + grp * CHUNK;

        float acc[8];
        #pragma unroll
        for (int k = 0; k < 8; ++k) acc[k] = 0.f;

        if (warp_base + 4 * CHUNK <= n_edges) {
            // ---------- clean path ----------
            int r_cur = __ldg(&row[base]);

            #pragma unroll
            for (int jb = 0; jb < CHUNK; jb += BATCH) {
                int   cc[BATCH]; float vv[BATCH]; int rn[BATCH]; uint4 raw[BATCH];

                // phase 1a: edge metadata (broadcast loads, issued back-to-back)
                #pragma unroll
                for (int u = 0; u < BATCH; ++u) {
                    int idx = base + jb + u;
                    cc[u] = __ldg(&col[idx]);
                    vv[u] = __ldg(&val[idx]);
                    rn[u] = (jb + u < CHUNK - 1) ? __ldg(&row[idx + 1]) : 0;
                }
                // phase 1b: 4 gathers in flight (MLP=4 per warp)
                #pragma unroll
                for (int u = 0; u < BATCH; ++u)
                    raw[u] = __ldg(&xq[(size_t)cc[u] * (D_FEAT / 8) + fl]);

                // phase 2: consume
                #pragma unroll
                for (int u = 0; u < BATCH; ++u) {
                    const __half2* hp = reinterpret_cast<const __half2*>(&raw[u]);
                    #pragma unroll
                    for (int k = 0; k < 4; ++k) {
                        float2 f = __half22float2(hp[k]);
                        acc[2 * k]     = fmaf(vv[u], f.x, acc[2 * k]);
                        acc[2 * k + 1] = fmaf(vv[u], f.y, acc[2 * k + 1]);
                    }

                    int flush, r_next;
                    if (jb + u == CHUNK - 1) {
                        flush = 1; r_next = r_cur;        // chunk end: always flush
                    } else {
                        r_next = rn[u];
                        flush = (r_next != r_cur);
                    }

                    if (__ballot_sync(0xffffffffu, flush)) {
                        float* dst = out + (size_t)r_cur * D_FEAT + fl * 8;
                        red_add_v4(dst,     acc[0], acc[1], acc[2], acc[3], flush);
                        red_add_v4(dst + 4, acc[4], acc[5], acc[6], acc[7], flush);
                        #pragma unroll
                        for (int k = 0; k < 8; ++k) acc[k] = flush ? 0.f : acc[k];
                    }
                    r_cur = r_next;
                }
            }
        } else {
            // ---------- guarded tail path (last warp-task only) ----------
            int last = n_edges - 1;
            if (last < 0) continue;
            int r_cur = __ldg(&row[min(base, last)]);

            #pragma unroll
            for (int j = 0; j < CHUNK; ++j) {
                int idx  = base + j;
                int idxc = min(idx, last);
                int   c = __ldg(&col[idxc]);
                float v = (idx <= last) ? __ldg(&val[idxc]) : 0.f;
                int r_next = __ldg(&row[min(idx + 1, last)]);

                uint4 raw = __ldg(&xq[(size_t)c * (D_FEAT / 8) + fl]);
                const __half2* hp = reinterpret_cast<const __half2*>(&raw);
                #pragma unroll
                for (int k = 0; k < 4; ++k) {
                    float2 f = __half22float2(hp[k]);
                    acc[2 * k]     = fmaf(v, f.x, acc[2 * k]);
                    acc[2 * k + 1] = fmaf(v, f.y, acc[2 * k + 1]);
                }

                int flush = (j == CHUNK - 1) || (r_next != r_cur) || (idx >= last);
                if (__ballot_sync(0xffffffffu, flush)) {
                    float* dst = out + (size_t)r_cur * D_FEAT + fl * 8;
                    red_add_v4(dst,     acc[0], acc[1], acc[2], acc[3], flush);
                    red_add_v4(dst + 4, acc[4], acc[5], acc[6], acc[7], flush);
                    #pragma unroll
                    for (int k = 0; k < 8; ++k) acc[k] = flush ? 0.f : acc[k];
                }
                r_cur = r_next;
            }
        }
    }
}

extern "C" void kernel_launch(void* const* d_in, const int* in_sizes, int n_in,
                              void* d_out, int out_size) {
    const int*   row = (const int*)d_in[0];
    const int*   col = (const int*)d_in[1];
    const float* val = (const float*)d_in[2];
    const float* x   = (const float*)d_in[3];
    float*       out = (float*)d_out;

    int n_edges = in_sizes[0];
    int n_x     = in_sizes[3];

    {
        int threads = 256;
        int n4 = n_x / 4;
        int n_out4 = out_size / 4;
        int conv_blocks = (n4 + threads - 1) / threads;
        int zero_blocks = (n_out4 + threads - 1) / threads;
        fused_prep_kernel<<<conv_blocks + zero_blocks, threads>>>(
            x, n4, out, n_out4, conv_blocks);
    }
    {
        int threads = 256;  // 8 warps/block; warp-task covers 4*CHUNK = 64 edges
        int n_tasks = (n_edges + 4 * CHUNK - 1) / (4 * CHUNK);
        int blocks = 1216;  // persistent: ~152 SMs x 8 blocks, no tail wave
        spmm_edge_chunk_kernel<<<blocks, threads>>>(row, col, val, out,
                                                    n_edges, n_tasks);
    }
}